// round 1
// baseline (speedup 1.0000x reference)
#include <cuda_runtime.h>

#define H 128
#define NCOLP 131072
#define NICP  2000
#define NBCP  2000
#define NTOT  (NCOLP + NICP + 2*NBCP)

#define NWARP 8
#define PPW   2                 // points per warp
#define NBLOCKS 148

// ---- dynamic smem layout (in floats) ----
#define OFF_WT  0                              // 3 * 128*128 interleaved weights
#define OFF_HB  (3*H*H)                        // per-warp h buffers: NWARP*PPW*4*H
#define OFF_RED (OFF_HB + NWARP*PPW*4*H)       // 16 doubles (block reduction)
#define SMEM_FLOATS (OFF_RED + 32)
#define SMEM_BYTES  (SMEM_FLOATS * 4)          // = 229,504 bytes

__device__ double g_acc;

// packed fp32x2 FMA: r = a*b + c elementwise on (lo,hi) pairs carried in b64
__device__ __forceinline__ unsigned long long ffma2(unsigned long long a,
                                                    unsigned long long b,
                                                    unsigned long long c) {
    unsigned long long r;
    asm("fma.rn.f32x2 %0, %1, %2, %3;" : "=l"(r) : "l"(a), "l"(b), "l"(c));
    return r;
}

__device__ __forceinline__ float pairsum(unsigned long long a) {
    float lo = __uint_as_float((unsigned)(a & 0xffffffffull));
    float hi = __uint_as_float((unsigned)(a >> 32));
    return lo + hi;
}

// SiLU value + 1st/2nd derivative propagation through one neuron
__device__ __forceinline__ void act4(float z, float zx, float zt, float zxx,
                                     float& a, float& ax, float& at_, float& axx) {
    float e   = __expf(-z);
    float s   = __fdividef(1.f, 1.f + e);
    float s1s = s * (1.f - s);
    float f1  = fmaf(z, s1s, s);                       // silu'
    float f2  = s1s * fmaf(z, fmaf(-2.f, s, 1.f), 2.f); // silu''
    a   = z * s;
    ax  = f1 * zx;
    at_ = f1 * zt;
    axx = fmaf(f2 * zx, zx, f1 * zxx);
}

extern "C" __global__ void __launch_bounds__(256, 1)
pinn_kernel(const float* __restrict__ x_col, const float* __restrict__ t_col,
            const float* __restrict__ x_ic,  const float* __restrict__ t_ic,
            const float* __restrict__ x_bcl, const float* __restrict__ x_bcr,
            const float* __restrict__ t_bc,
            const float* __restrict__ W0, const float* __restrict__ b0,
            const float* __restrict__ W1, const float* __restrict__ b1,
            const float* __restrict__ W2, const float* __restrict__ b2,
            const float* __restrict__ W3, const float* __restrict__ b3,
            const float* __restrict__ W4, const float* __restrict__ b4,
            const float* __restrict__ pD, const float* __restrict__ pchi)
{
    extern __shared__ float smem[];
    const int tid  = threadIdx.x;
    const int lane = tid & 31;
    const int warp = tid >> 5;

    // ---- load + interleave hidden weights into smem ----
    // element (i,j) of W stored at [(i>>1)*256 + 2*j + (i&1)]
    // so that a b64 load at [ip*256 + 2*j] yields the (even,odd) K-pair for column j.
    {
        const float* src[3] = {W1, W2, W3};
        for (int k = 0; k < 3; ++k) {
            float* dst = smem + OFF_WT + k * (H*H);
            for (int idx = tid; idx < H*H; idx += blockDim.x) {
                int i = idx >> 7, j = idx & 127;
                dst[(i >> 1) * 256 + (j << 1) + (i & 1)] = src[k][idx];
            }
        }
    }
    __syncthreads();

    // ---- per-lane constant preloads (lane owns j = lane + 32c) ----
    float w0x[4], w0t[4], b0c[4], bc1[4], bc2[4], bc3[4], w4c[4];
    #pragma unroll
    for (int c = 0; c < 4; ++c) {
        int j = lane + 32 * c;
        w0x[c] = W0[j]; w0t[c] = W0[H + j]; b0c[c] = b0[j];
        bc1[c] = b1[j]; bc2[c] = b2[j];     bc3[c] = b3[j];
        w4c[c] = W4[j];
    }
    const float b4v  = b4[0];
    const float Dv   = pD[0];
    const float chiv = pchi[0];

    float* hb = smem + OFF_HB + warp * (PPW * 4 * H);  // [p][v][H]

    double local = 0.0;

    const int stride = gridDim.x * NWARP * PPW;
    for (int base = (blockIdx.x * NWARP + warp) * PPW; base < NTOT; base += stride) {

        // ---- fetch points + classify ----
        float px[PPW], pt[PPW]; int ptype[PPW];
        #pragma unroll
        for (int p = 0; p < PPW; ++p) {
            int pid = base + p;
            float x = 0.f, t = 0.f; int ty = 3;
            if (pid < NCOLP)                    { x = x_col[pid];               t = t_col[pid];             ty = 0; }
            else if (pid < NCOLP + NICP)        { int q = pid - NCOLP;          x = x_ic[q];  t = t_ic[q];  ty = 1; }
            else if (pid < NCOLP + NICP + NBCP) { int q = pid - NCOLP - NICP;   x = x_bcl[q]; t = t_bc[q];  ty = 2; }
            else if (pid < NTOT)                { int q = pid - NCOLP-NICP-NBCP;x = x_bcr[q]; t = t_bc[q];  ty = 2; }
            px[p] = x; pt[p] = t; ptype[p] = ty;
        }

        // ---- layer 0 (2 -> 128), streams: val, d/dx, d/dt, d2/dx2 ----
        #pragma unroll
        for (int p = 0; p < PPW; ++p) {
            #pragma unroll
            for (int c = 0; c < 4; ++c) {
                int j = lane + 32 * c;
                float z = fmaf(px[p], w0x[c], fmaf(pt[p], w0t[c], b0c[c]));
                float a, ax, at_, axx;
                act4(z, w0x[c], w0t[c], 0.f, a, ax, at_, axx);
                hb[(p*4 + 0)*H + j] = a;
                hb[(p*4 + 1)*H + j] = ax;
                hb[(p*4 + 2)*H + j] = at_;
                hb[(p*4 + 3)*H + j] = axx;
            }
        }
        __syncwarp();

        // ---- hidden layers 1..3 (128 -> 128), f32x2 mainloop ----
        float cur[PPW][4][4];   // final-layer activations stay in regs
        #pragma unroll 1
        for (int L = 0; L < 3; ++L) {
            const float* Wt = smem + OFF_WT + L * (H*H);
            unsigned long long acc[PPW][4][4];
            #pragma unroll
            for (int p = 0; p < PPW; ++p)
                #pragma unroll
                for (int v = 0; v < 4; ++v)
                    #pragma unroll
                    for (int c = 0; c < 4; ++c) acc[p][v][c] = 0ull;

            #pragma unroll 4
            for (int i4 = 0; i4 < 32; ++i4) {
                const int i = i4 * 4;
                unsigned long long w[2][4];
                #pragma unroll
                for (int pr = 0; pr < 2; ++pr)
                    #pragma unroll
                    for (int c = 0; c < 4; ++c)
                        w[pr][c] = *(const unsigned long long*)
                            &Wt[(2*i4 + pr) * 256 + 2*lane + 64*c];
                #pragma unroll
                for (int p = 0; p < PPW; ++p)
                    #pragma unroll
                    for (int v = 0; v < 4; ++v) {
                        ulonglong2 h2 = *(const ulonglong2*)&hb[(p*4 + v)*H + i];
                        #pragma unroll
                        for (int c = 0; c < 4; ++c) {
                            acc[p][v][c] = ffma2(h2.x, w[0][c], acc[p][v][c]);
                            acc[p][v][c] = ffma2(h2.y, w[1][c], acc[p][v][c]);
                        }
                    }
            }
            __syncwarp();   // all reads of hb done before overwrite

            const bool last = (L == 2);
            #pragma unroll
            for (int p = 0; p < PPW; ++p)
                #pragma unroll
                for (int c = 0; c < 4; ++c) {
                    float bb  = (L == 0) ? bc1[c] : ((L == 1) ? bc2[c] : bc3[c]);
                    float z   = pairsum(acc[p][0][c]) + bb;
                    float zx  = pairsum(acc[p][1][c]);
                    float zt  = pairsum(acc[p][2][c]);
                    float zxx = pairsum(acc[p][3][c]);
                    float a, ax, at_, axx;
                    act4(z, zx, zt, zxx, a, ax, at_, axx);
                    if (!last) {
                        int j = lane + 32 * c;
                        hb[(p*4 + 0)*H + j] = a;
                        hb[(p*4 + 1)*H + j] = ax;
                        hb[(p*4 + 2)*H + j] = at_;
                        hb[(p*4 + 3)*H + j] = axx;
                    } else {
                        cur[p][0][c] = a;  cur[p][1][c] = ax;
                        cur[p][2][c] = at_; cur[p][3][c] = axx;
                    }
                }
            if (!last) __syncwarp();
        }

        // ---- output layer (128 -> 1) + loss contribution ----
        #pragma unroll
        for (int p = 0; p < PPW; ++p) {
            float s0 = 0.f, s1 = 0.f, s2 = 0.f, s3 = 0.f;
            #pragma unroll
            for (int c = 0; c < 4; ++c) {
                s0 = fmaf(cur[p][0][c], w4c[c], s0);
                s1 = fmaf(cur[p][1][c], w4c[c], s1);
                s2 = fmaf(cur[p][2][c], w4c[c], s2);
                s3 = fmaf(cur[p][3][c], w4c[c], s3);
            }
            #pragma unroll
            for (int off = 16; off; off >>= 1) {
                s0 += __shfl_xor_sync(0xffffffffu, s0, off);
                s1 += __shfl_xor_sync(0xffffffffu, s1, off);
                s2 += __shfl_xor_sync(0xffffffffu, s2, off);
                s3 += __shfl_xor_sync(0xffffffffu, s3, off);
            }
            if (lane == 0) {
                float u = s0 + b4v, ux = s1, ut = s2, uxx = s3;
                float x = px[p];
                float contrib = 0.f;
                int ty = ptype[p];
                if (ty == 0) {
                    float a   = x - 0.7f;
                    float E   = __expf(-50.f * a * a);
                    float dS  = -100.f * a * E;                      // _dSdx
                    float dS2 = 100.f * E * fmaf(100.f * a, a, -1.f); // d/dx _dSdx
                    float res = ut - Dv * uxx + chiv * (ux * dS + u * dS2);
                    contrib = res * res * (1.f / NCOLP);
                } else if (ty == 1) {
                    float dxx_ = x - 0.3f;
                    float icv  = 0.1f + 0.05f * __expf(-100.f * dxx_ * dxx_);
                    float d    = u - icv;
                    contrib = d * d * (1.f / NICP);
                } else if (ty == 2) {
                    contrib = ux * ux * (1.f / NBCP);
                }
                local += (double)contrib;
            }
        }
    }

    // ---- block reduction -> global double accumulator ----
    double* red = (double*)(smem + OFF_RED);
    __syncthreads();
    if (lane == 0) red[warp] = local;
    __syncthreads();
    if (tid == 0) {
        double s = 0.0;
        #pragma unroll
        for (int w = 0; w < NWARP; ++w) s += red[w];
        atomicAdd(&g_acc, s);
    }
}

__global__ void k_zero() { g_acc = 0.0; }
__global__ void k_final(float* out) { out[0] = (float)g_acc; }

extern "C" void kernel_launch(void* const* d_in, const int* in_sizes, int n_in,
                              void* d_out, int out_size) {
    (void)in_sizes; (void)n_in; (void)out_size;
    cudaFuncSetAttribute(pinn_kernel,
                         cudaFuncAttributeMaxDynamicSharedMemorySize, SMEM_BYTES);
    k_zero<<<1, 1>>>();
    pinn_kernel<<<NBLOCKS, 256, SMEM_BYTES>>>(
        (const float*)d_in[0],  (const float*)d_in[1],  (const float*)d_in[2],
        (const float*)d_in[3],  (const float*)d_in[4],  (const float*)d_in[5],
        (const float*)d_in[6],  (const float*)d_in[7],  (const float*)d_in[8],
        (const float*)d_in[9],  (const float*)d_in[10], (const float*)d_in[11],
        (const float*)d_in[12], (const float*)d_in[13], (const float*)d_in[14],
        (const float*)d_in[15], (const float*)d_in[16], (const float*)d_in[17],
        (const float*)d_in[18]);
    k_final<<<1, 1>>>((float*)d_out);
}